// round 15
// baseline (speedup 1.0000x reference)
#include <cuda_runtime.h>
#include <cuda_bf16.h>

// USER_NUM=1000, SKILL_NUM=256, K_HIDDEN=128, N_ITEMS=4096, SEQ_LEN=8192
// out[l, k] = sum_{s : Q[items[l], s] != 0} E[user, s, k]
//
// Two-kernel, split-K x4:
//   Phase A: one warp per (item, quarter-of-skills). nnz ~ 6.4 -> typically a
//            single predicated batch of 8 gathers in flight (1 latency round).
//   Phase B: out[l] = sum of 4 partials of items[l] (L2-resident combine).

#define SEQ_LEN   8192
#define N_ITEMS   4096
#define SKILLS    256
#define K_HIDDEN  128
#define NNZ_CAP   32          // binomial(64,0.1): mean 6.4, std 2.4 -> 32 is huge margin
#define WPC_A     8
#define THR_B     256

// Partial sums: 16384 x 32 float4 = 8 MB static device scratch (no alloc)
__device__ float4 g_part4[4 * N_ITEMS * (K_HIDDEN / 4)];

// ---------------- Phase A: per-(item,quarter) sparse partial row-sum ----------------
__global__ void __launch_bounds__(WPC_A * 32)
kquarter_rowsum(const int* __restrict__ user_p,
                const float* __restrict__ Q,     // [N_ITEMS, SKILLS]
                const float* __restrict__ emb)   // [USER_NUM, SKILLS, K_HIDDEN]
{
    __shared__ int sidx[WPC_A][NNZ_CAP];

    const int tid  = threadIdx.x;
    const int w    = tid >> 5;
    const int lane = tid & 31;
    const int task = blockIdx.x * WPC_A + w;    // 0 .. 4*N_ITEMS-1
    const int item = task >> 2;
    const int quar = task & 3;                  // skills quar*64 .. quar*64+63

    const int user = user_p[0];
    const float4* __restrict__ E4 =
        reinterpret_cast<const float4*>(emb + (long long)user * SKILLS * K_HIDDEN) + lane;

    // This quarter's 64 skills: one coalesced float2 per lane (LDG.64)
    const float2 v = reinterpret_cast<const float2*>(
        Q + (long long)item * SKILLS + quar * 64)[lane];

    // Ballot-compact nonzero skill ids (2 ballots)
    const int s_base = quar * 64 + 2 * lane;
    const float vals[2] = {v.x, v.y};
    const unsigned lt_mask = (1u << lane) - 1u;
    int nnz = 0;
    #pragma unroll
    for (int t = 0; t < 2; t++) {
        const bool nz = (vals[t] != 0.0f);
        const unsigned m = __ballot_sync(0xffffffffu, nz);
        if (nz) {
            const int p = nnz + __popc(m & lt_mask);
            if (p < NNZ_CAP) sidx[w][p] = s_base + t;
        }
        nnz += __popc(m);
    }
    __syncwarp();
    nnz = min(nnz, NNZ_CAP);

    // Gather-accumulate: predicated batches of 8 -> typical nnz 6.4 = ONE batch
    float4 acc = make_float4(0.f, 0.f, 0.f, 0.f);
    for (int j0 = 0; j0 < nnz; j0 += 8) {
        float4 e[8];
        #pragma unroll
        for (int t = 0; t < 8; t++) {
            const int j = j0 + t;
            if (j < nnz) {
                e[t] = E4[sidx[w][j] * 32];
            } else {
                e[t] = make_float4(0.f, 0.f, 0.f, 0.f);
            }
        }
        acc.x += ((e[0].x + e[1].x) + (e[2].x + e[3].x))
               + ((e[4].x + e[5].x) + (e[6].x + e[7].x));
        acc.y += ((e[0].y + e[1].y) + (e[2].y + e[3].y))
               + ((e[4].y + e[5].y) + (e[6].y + e[7].y));
        acc.z += ((e[0].z + e[1].z) + (e[2].z + e[3].z))
               + ((e[4].z + e[5].z) + (e[6].z + e[7].z));
        acc.w += ((e[0].w + e[1].w) + (e[2].w + e[3].w))
               + ((e[4].w + e[5].w) + (e[6].w + e[7].w));
    }

    g_part4[task * 32 + lane] = acc;   // quarters of an item adjacent (512B stride)
}

// ---------------- Phase B: out[l] = sum of 4 partials ----------------
__global__ void __launch_bounds__(THR_B)
kcombine4(const int* __restrict__ items,   // [SEQ_LEN]
          float4* __restrict__ out4)       // [SEQ_LEN * 32]
{
    const int g   = blockIdx.x * THR_B + threadIdx.x;   // 0 .. 262143, exact
    const int pos = g >> 5;
    const int q   = g & 31;
    const int it  = __ldg(&items[pos]);
    const int base = it * 4;

    // 4 independent LDG.128 within a 2KB neighborhood (L2-resident scratch)
    const float4 r0 = g_part4[(base + 0) * 32 + q];
    const float4 r1 = g_part4[(base + 1) * 32 + q];
    const float4 r2 = g_part4[(base + 2) * 32 + q];
    const float4 r3 = g_part4[(base + 3) * 32 + q];

    float4 o;
    o.x = (r0.x + r1.x) + (r2.x + r3.x);
    o.y = (r0.y + r1.y) + (r2.y + r3.y);
    o.z = (r0.z + r1.z) + (r2.z + r3.z);
    o.w = (r0.w + r1.w) + (r2.w + r3.w);
    out4[g] = o;
}

extern "C" void kernel_launch(void* const* d_in, const int* in_sizes, int n_in,
                              void* d_out, int out_size)
{
    const int*   user  = nullptr;
    const float* Q     = nullptr;
    const int*   items = nullptr;
    const float* emb   = nullptr;

    for (int i = 0; i < n_in; i++) {
        switch (in_sizes[i]) {
            case 1:                        user  = (const int*)  d_in[i]; break;
            case N_ITEMS * SKILLS:         Q     = (const float*)d_in[i]; break;
            case SEQ_LEN:                  items = (const int*)  d_in[i]; break;
            case 1000 * SKILLS * K_HIDDEN: emb   = (const float*)d_in[i]; break;
            default: break;
        }
    }
    if (!user)  user  = (const int*)  d_in[0];
    if (!Q)     Q     = (const float*)d_in[1];
    if (!items) items = (const int*)  d_in[2];
    if (!emb)   emb   = (const float*)d_in[3];

    // Phase A: 4 warps per item -> 16384 warps -> 2048 CTAs x 256 threads
    kquarter_rowsum<<<(4 * N_ITEMS) / WPC_A, WPC_A * 32>>>(user, Q, emb);

    // Phase B: 1 float4 per thread -> 1024 CTAs x 256 threads
    kcombine4<<<(SEQ_LEN * (K_HIDDEN / 4)) / THR_B, THR_B>>>(items, (float4*)d_out);
}